// round 10
// baseline (speedup 1.0000x reference)
#include <cuda_runtime.h>

#define NLEV 16
#define LOG2_T 19
#define TSIZE (1u << LOG2_T)
#define TMASK (TSIZE - 1u)
#define PRIME_Y 2654435761u
#define PRIME_Z 805459861u

#define CAP   2200000
#define NBINS 32768          // 15-bit Morton key at res 32
#define FSTR  128            // lane stride for smem staging (128 threads/CTA)

typedef unsigned long long ull;

// Static scratch (allocation-free): sorted coords, permutation, histogram.
__device__ float4   g_xs[CAP];
__device__ int      g_perm[CAP];
__device__ unsigned g_hist[NBINS];

// ---------------- sorting pre-pass (unchanged from R5 best) ----------------

__device__ __forceinline__ unsigned morton_key(float x0, float x1, float x2) {
    int cx = (int)(x0 * 32.0f); cx = cx < 0 ? 0 : (cx > 31 ? 31 : cx);
    int cy = (int)(x1 * 32.0f); cy = cy < 0 ? 0 : (cy > 31 ? 31 : cy);
    int cz = (int)(x2 * 32.0f); cz = cz < 0 ? 0 : (cz > 31 ? 31 : cz);
    unsigned m = 0;
    #pragma unroll
    for (int d = 0; d < 5; d++) {
        m |= ((unsigned)(cx >> d) & 1u) << (3 * d + 0);
        m |= ((unsigned)(cy >> d) & 1u) << (3 * d + 1);
        m |= ((unsigned)(cz >> d) & 1u) << (3 * d + 2);
    }
    return m;
}

__global__ void zero_hist_k() {
    int i = blockIdx.x * blockDim.x + threadIdx.x;
    if (i < NBINS) g_hist[i] = 0u;
}

__global__ void hist_k(const float* __restrict__ x, int N) {
    int i = blockIdx.x * blockDim.x + threadIdx.x;
    if (i >= N) return;
    float x0 = x[3 * i + 0] * 0.5f + 0.5f;
    float x1 = x[3 * i + 1] * 0.5f + 0.5f;
    float x2 = x[3 * i + 2] * 0.5f + 0.5f;
    atomicAdd(&g_hist[morton_key(x0, x1, x2)], 1u);
}

__global__ void scan_k() {
    __shared__ unsigned sm[1024];
    const int t = threadIdx.x;
    unsigned vals[32];
    unsigned s = 0;
    #pragma unroll
    for (int k = 0; k < 32; k++) { vals[k] = g_hist[t * 32 + k]; s += vals[k]; }
    sm[t] = s;
    __syncthreads();
    for (int off = 1; off < 1024; off <<= 1) {
        unsigned v = (t >= off) ? sm[t - off] : 0u;
        __syncthreads();
        sm[t] += v;
        __syncthreads();
    }
    unsigned run = sm[t] - s;
    #pragma unroll
    for (int k = 0; k < 32; k++) { g_hist[t * 32 + k] = run; run += vals[k]; }
}

__global__ void scatter_k(const float* __restrict__ x, int N) {
    int i = blockIdx.x * blockDim.x + threadIdx.x;
    if (i >= N) return;
    float x0 = x[3 * i + 0] * 0.5f + 0.5f;
    float x1 = x[3 * i + 1] * 0.5f + 0.5f;
    float x2 = x[3 * i + 2] * 0.5f + 0.5f;
    unsigned key = morton_key(x0, x1, x2);
    unsigned slot = atomicAdd(&g_hist[key], 1u);
    g_xs[slot] = make_float4(x0, x1, x2, 0.0f);
    g_perm[slot] = i;
}

// ---------------- main fused kernel ----------------

__device__ __forceinline__ ull fma2u(ull a, ull b, ull c) {
    ull d;
    asm("fma.rn.f32x2 %0, %1, %2, %3;" : "=l"(d) : "l"(a), "l"(b), "l"(c));
    return d;
}
__device__ __forceinline__ ull pack2(float lo, float hi) {
    ull r;
    asm("mov.b64 %0, {%1, %2};" : "=l"(r) : "f"(lo), "f"(hi));
    return r;
}
__device__ __forceinline__ void unpack2(ull v, float& lo, float& hi) {
    asm("mov.b64 {%0, %1}, %2;" : "=f"(lo), "=f"(hi) : "l"(v));
}

// Encode one point's 16-level hash features. ISA=true: write to smem staging
// fs[k*FSTR+tid] (own slot, no sync needed). ISA=false: pack into featB regs.
template<bool ISA>
__device__ __forceinline__ void encode_point(
    float x0, float x1, float x2,
    const float2* __restrict__ tables, const float* __restrict__ sRes,
    float* __restrict__ fs, int tid, ull* featB)
{
    float2   tbuf[2][8];
    float    wbuf[2][3];
    unsigned mbuf[2];

    auto issue = [&](int L, float2* tb, float* wb, unsigned& mb) {
        const float res = sRes[L];
        const float px = x0 * res, py = x1 * res, pz = x2 * res;
        const float fx = floorf(px), fy = floorf(py), fz = floorf(pz);
        wb[0] = px - fx; wb[1] = py - fy; wb[2] = pz - fz;
        const unsigned cx = (unsigned)fx, cy = (unsigned)fy, cz = (unsigned)fz;
        const unsigned hy0 = cy * PRIME_Y, hy1 = hy0 + PRIME_Y;
        const unsigned hz0 = cz * PRIME_Z, hz1 = hz0 + PRIME_Z;
        unsigned rr[4];
        rr[0] = hy0 ^ hz0; rr[1] = hy1 ^ hz0; rr[2] = hy0 ^ hz1; rr[3] = hy1 ^ hz1;
        const float2* __restrict__ base = tables + (size_t)L * TSIZE;
        unsigned m = 0;
        if (!(cx & 1u)) {
            #pragma unroll
            for (int j = 0; j < 4; j++) {
                const unsigned i0 = (cx ^ rr[j]) & TMASK;
                m |= (i0 & 1u) << j;
                const float4 v = __ldg((const float4*)(base + (i0 & ~1u)));
                tb[2 * j]     = make_float2(v.x, v.y);
                tb[2 * j + 1] = make_float2(v.z, v.w);
            }
        } else {
            #pragma unroll
            for (int j = 0; j < 4; j++) {
                const unsigned i0 = (cx        ^ rr[j]) & TMASK;
                const unsigned i1 = ((cx + 1u) ^ rr[j]) & TMASK;
                tb[2 * j]     = __ldg(base + i0);
                tb[2 * j + 1] = __ldg(base + i1);
            }
        }
        mb = m;
    };

    issue(0, tbuf[0], wbuf[0], mbuf[0]);

    #pragma unroll
    for (int L = 0; L < NLEV; L++) {
        const int cur = L & 1;
        if (L < NLEV - 1) issue(L + 1, tbuf[cur ^ 1], wbuf[cur ^ 1], mbuf[cur ^ 1]);

        const float wx1 = wbuf[cur][0], wy1 = wbuf[cur][1], wz1 = wbuf[cur][2];
        const float wx0 = 1.0f - wx1, wy0 = 1.0f - wy1, wz0 = 1.0f - wz1;
        float wyz[4];
        wyz[0] = wy0 * wz0; wyz[1] = wy1 * wz0; wyz[2] = wy0 * wz1; wyz[3] = wy1 * wz1;
        const float2* t = tbuf[cur];
        const unsigned m = mbuf[cur];
        float f0 = 0.0f, f1 = 0.0f;
        #pragma unroll
        for (int j = 0; j < 4; j++) {
            const bool  s  = (m >> j) & 1u;
            const float wl = s ? wx1 : wx0;
            const float wh = s ? wx0 : wx1;
            const float cl = wl * wyz[j], ch = wh * wyz[j];
            f0 += cl * t[2 * j].x + ch * t[2 * j + 1].x;
            f1 += cl * t[2 * j].y + ch * t[2 * j + 1].y;
        }
        if (ISA) {
            fs[(2 * L)     * FSTR + tid] = f0;
            fs[(2 * L + 1) * FSTR + tid] = f1;
        } else {
            featB[L] = pack2(f0, f1);
        }
    }
}

// dyn smem layout (floats): W1 2048 | W2 4096 | b1 64 | b2 64 | W3 64 | res 32
//                           | fs 32*128 | h1s 64*128
#define SM_W1   0
#define SM_W2   2048
#define SM_B1   (2048 + 4096)
#define SM_B2   (SM_B1 + 64)
#define SM_W3   (SM_B2 + 64)
#define SM_RES  (SM_W3 + 64)
#define SM_FS   (SM_RES + 32)
#define SM_H1   (SM_FS + 32 * FSTR)
#define SM_TOT  (SM_H1 + 64 * FSTR)          // 18656 floats = 74624 bytes

__global__ __launch_bounds__(128, 3)
void hashgrid_mlp_kernel(const float2* __restrict__ tables,
                         const float*  __restrict__ resolutions,
                         const float*  __restrict__ W1, const float* __restrict__ b1,
                         const float*  __restrict__ W2, const float* __restrict__ b2,
                         const float*  __restrict__ W3, const float* __restrict__ b3,
                         float* __restrict__ out, int N)
{
    extern __shared__ __align__(16) float smem[];
    float* sW1  = smem + SM_W1;
    float* sW2  = smem + SM_W2;
    float* sB1  = smem + SM_B1;
    float* sB2  = smem + SM_B2;
    float* sW3  = smem + SM_W3;
    float* sRes = smem + SM_RES;
    float* fs   = smem + SM_FS;
    float* h1s  = smem + SM_H1;

    const int tid = threadIdx.x;
    for (int k = tid; k < 2048; k += 128) sW1[k] = W1[k];
    for (int k = tid; k < 4096; k += 128) sW2[k] = W2[k];
    if (tid < 64) { sB1[tid] = b1[tid]; sB2[tid] = b2[tid]; sW3[tid] = W3[tid]; }
    if (tid < 16) sRes[tid] = resolutions[tid];
    if (tid == 0) sRes[16] = b3[0];
    __syncthreads();

    // each thread handles two points: A = base+tid, B = base+128+tid
    const int base = blockIdx.x * 256;
    int iA = base + tid;        if (iA >= N) iA = N - 1;
    int iB = base + 128 + tid;  if (iB >= N) iB = N - 1;

    const float4 xA = g_xs[iA];
    const float4 xB = g_xs[iB];

    // ---- encode: A features -> smem staging, B features -> regs ----
    ull featB[16];
    encode_point<true >(xA.x, xA.y, xA.z, tables, sRes, fs, tid, featB);
    encode_point<false>(xB.x, xB.y, xB.z, tables, sRes, fs, tid, featB);

    // ---- layer 1: k-inner GEMM, weights loaded ONCE for both points ----
    // output neurons tiled 2 x 32; A's h1 -> smem, B's h1 -> regs
    ull accA[16], accB[16];
    ull hB0[16], hB1[16];

    #pragma unroll
    for (int t = 0; t < 2; t++) {
        #pragma unroll
        for (int m = 0; m < 16; m++) {
            const ull bb = ((const ull*)(sB1 + t * 32))[m];
            accA[m] = bb; accB[m] = bb;
        }
        #pragma unroll
        for (int k = 0; k < 32; k++) {
            const float vA = fs[k * FSTR + tid];
            float lo, hi; unpack2(featB[k >> 1], lo, hi);
            const float vB = (k & 1) ? hi : lo;
            const ull aA = pack2(vA, vA), aB = pack2(vB, vB);
            const ulonglong2* w = (const ulonglong2*)(sW1 + k * 64 + t * 32);
            #pragma unroll
            for (int j = 0; j < 8; j++) {
                const ulonglong2 W = w[j];                 // LDS.128 broadcast
                accA[2 * j]     = fma2u(aA, W.x, accA[2 * j]);
                accA[2 * j + 1] = fma2u(aA, W.y, accA[2 * j + 1]);
                accB[2 * j]     = fma2u(aB, W.x, accB[2 * j]);
                accB[2 * j + 1] = fma2u(aB, W.y, accB[2 * j + 1]);
            }
        }
        // relu; A tile -> smem, B tile -> regs
        #pragma unroll
        for (int m = 0; m < 16; m++) {
            float e0, e1;
            unpack2(accA[m], e0, e1);
            h1s[(t * 32 + 2 * m)     * FSTR + tid] = fmaxf(e0, 0.0f);
            h1s[(t * 32 + 2 * m + 1) * FSTR + tid] = fmaxf(e1, 0.0f);
            unpack2(accB[m], e0, e1);
            const ull hb = pack2(fmaxf(e0, 0.0f), fmaxf(e1, 0.0f));
            if (t == 0) hB0[m] = hb; else hB1[m] = hb;
        }
    }

    // ---- layer 2 + layer 3: weights loaded once per pair ----
    float outA = sRes[16], outB = sRes[16];
    #pragma unroll
    for (int t = 0; t < 2; t++) {
        #pragma unroll
        for (int m = 0; m < 16; m++) {
            const ull bb = ((const ull*)(sB2 + t * 32))[m];
            accA[m] = bb; accB[m] = bb;
        }
        #pragma unroll
        for (int k = 0; k < 64; k++) {
            const float vA = h1s[k * FSTR + tid];
            float lo, hi;
            unpack2((k < 32 ? hB0 : hB1)[(k & 31) >> 1], lo, hi);
            const float vB = (k & 1) ? hi : lo;
            const ull aA = pack2(vA, vA), aB = pack2(vB, vB);
            const ulonglong2* w = (const ulonglong2*)(sW2 + k * 64 + t * 32);
            #pragma unroll
            for (int j = 0; j < 8; j++) {
                const ulonglong2 W = w[j];                 // LDS.128 broadcast
                accA[2 * j]     = fma2u(aA, W.x, accA[2 * j]);
                accA[2 * j + 1] = fma2u(aA, W.y, accA[2 * j + 1]);
                accB[2 * j]     = fma2u(aB, W.x, accB[2 * j]);
                accB[2 * j + 1] = fma2u(aB, W.y, accB[2 * j + 1]);
            }
        }
        #pragma unroll
        for (int m = 0; m < 16; m++) {
            const float w30 = sW3[t * 32 + 2 * m];
            const float w31 = sW3[t * 32 + 2 * m + 1];
            float e0, e1;
            unpack2(accA[m], e0, e1);
            outA += fmaxf(e0, 0.0f) * w30 + fmaxf(e1, 0.0f) * w31;
            unpack2(accB[m], e0, e1);
            outB += fmaxf(e0, 0.0f) * w30 + fmaxf(e1, 0.0f) * w31;
        }
    }

    if (base + tid       < N) out[g_perm[iA]] = outA;
    if (base + 128 + tid < N) out[g_perm[iB]] = outB;
}

extern "C" void kernel_launch(void* const* d_in, const int* in_sizes, int n_in,
                              void* d_out, int out_size)
{
    const float*  x    = (const float*) d_in[0];
    const float2* tabs = (const float2*)d_in[1];
    const float*  res  = (const float*) d_in[2];
    const float*  W1   = (const float*) d_in[3];
    const float*  b1   = (const float*) d_in[4];
    const float*  W2   = (const float*) d_in[5];
    const float*  b2   = (const float*) d_in[6];
    const float*  W3   = (const float*) d_in[7];
    const float*  b3   = (const float*) d_in[8];

    const int N = in_sizes[0] / 3;

    // spatial binning presort (all graph-capturable kernel launches)
    {
        const int threads = 256;
        const int blocks = (N + threads - 1) / threads;
        zero_hist_k<<<(NBINS + 255) / 256, 256>>>();
        hist_k<<<blocks, threads>>>(x, N);
        scan_k<<<1, 1024>>>();
        scatter_k<<<blocks, threads>>>(x, N);
    }

    const int smem_bytes = SM_TOT * (int)sizeof(float);   // 74624
    cudaFuncSetAttribute(hashgrid_mlp_kernel,
                         cudaFuncAttributeMaxDynamicSharedMemorySize, smem_bytes);

    const int blocks = (N + 255) / 256;                   // 2 points per thread
    hashgrid_mlp_kernel<<<blocks, 128, smem_bytes>>>(tabs, res, W1, b1, W2, b2,
                                                     W3, b3, (float*)d_out, N);
}